// round 16
// baseline (speedup 1.0000x reference)
#include <cuda_runtime.h>
#include <cuda_fp16.h>
#include <math.h>
#include <stdint.h>

#define BB 2
#define TT 2048
#define DD 1024
#define HH 16
#define DH 64
#define NTOK (BB*TT)
#define NCH 16                  // 1024 / 64 K-chunks
#define ROWB 144                // gemm smem row stride bytes (128B data + 16 pad)
#define A_BYTES (128*ROWB)      // 18432
#define STAGE_B (A_BYTES + 64*ROWB)  // 27648
#define GEMM_SMEM (2*STAGE_B)        // 55296
#define QSCALE 0.1803368801f    // log2(e) / sqrt(64)

// flash smem geometry
#define FROW 144
#define FSTG_K 9216
#define FSTG   18432
#define FSMEM  36864

// Scratch (allocation forbidden; __device__ globals are the sanctioned path)
__device__ __half g_xh[NTOK*DD];                    // x in fp16
__device__ __half g_qh[NTOK*DD];                    // pre-scaled by QSCALE
__device__ __half g_kh[NTOK*DD];
__device__ __half g_vh[NTOK*DD];
__device__ __half g_ch[NTOK*DD];                    // ctx in fp16
__device__ __half g_wbuf[(size_t)3*DD*DD];          // Wq|Wk|Wv fp16
__device__ __half g_wobuf[(size_t)DD*DD];           // Wo fp16

// ---------------------------------------------------------------------------
// PTX helpers
// ---------------------------------------------------------------------------
__device__ __forceinline__ uint32_t smem_u32(const void* p) {
    uint32_t a;
    asm("{ .reg .u64 t; cvta.to.shared.u64 t, %1; cvt.u32.u64 %0, t; }" : "=r"(a) : "l"(p));
    return a;
}
__device__ __forceinline__ void cpasync16(uint32_t saddr, const void* gaddr) {
    asm volatile("cp.async.cg.shared.global [%0], [%1], 16;" :: "r"(saddr), "l"(gaddr) : "memory");
}
__device__ __forceinline__ void cp_commit() { asm volatile("cp.async.commit_group;" ::: "memory"); }
__device__ __forceinline__ void cp_wait0()  { asm volatile("cp.async.wait_group 0;" ::: "memory"); }
__device__ __forceinline__ void cp_wait1()  { asm volatile("cp.async.wait_group 1;" ::: "memory"); }

__device__ __forceinline__ void ldmx4(uint32_t* r, uint32_t addr) {
    asm volatile("ldmatrix.sync.aligned.m8n8.x4.shared.b16 {%0,%1,%2,%3}, [%4];"
                 : "=r"(r[0]), "=r"(r[1]), "=r"(r[2]), "=r"(r[3]) : "r"(addr));
}
__device__ __forceinline__ void ldmx4t(uint32_t* r, uint32_t addr) {
    asm volatile("ldmatrix.sync.aligned.m8n8.x4.trans.shared.b16 {%0,%1,%2,%3}, [%4];"
                 : "=r"(r[0]), "=r"(r[1]), "=r"(r[2]), "=r"(r[3]) : "r"(addr));
}
__device__ __forceinline__ void mma_fp16(float* c, const uint32_t* a, uint32_t b0, uint32_t b1) {
    asm volatile(
        "mma.sync.aligned.m16n8k16.row.col.f32.f16.f16.f32 "
        "{%0,%1,%2,%3}, {%4,%5,%6,%7}, {%8,%9}, {%0,%1,%2,%3};"
        : "+f"(c[0]), "+f"(c[1]), "+f"(c[2]), "+f"(c[3])
        : "r"(a[0]), "r"(a[1]), "r"(a[2]), "r"(a[3]), "r"(b0), "r"(b1));
}
__device__ __forceinline__ uint32_t packh2(float lo, float hi) {
    uint32_t u;
    asm("cvt.rn.f16x2.f32 %0, %1, %2;" : "=r"(u) : "f"(hi), "f"(lo));
    return u;
}
__device__ __forceinline__ float exp2_mufu(float y) {
    float r;
    asm("ex2.approx.f32 %0, %1;" : "=f"(r) : "f"(y));
    return r;
}

// ---------------------------------------------------------------------------
// Fused prep: fp32 -> fp16 for x + all four weight matrices, one launch.
// ---------------------------------------------------------------------------
__global__ void prep_all(const float* __restrict__ x,
                         const float* __restrict__ Wq, const float* __restrict__ Wk,
                         const float* __restrict__ Wv, const float* __restrict__ Wo)
{
    int i = (blockIdx.x * 256 + threadIdx.x) * 4;
    const float* src;
    __half* dst;
    int off;
    if (i < NTOK*DD) {
        src = x; dst = g_xh; off = i;
    } else {
        int j = i - NTOK*DD;
        int w = j >> 20;
        off = j & ((1 << 20) - 1);
        src = (w == 0) ? Wq : (w == 1) ? Wk : (w == 2) ? Wv : Wo;
        dst = (w == 3) ? g_wobuf : g_wbuf + (size_t)w * DD * DD;
    }
    float4 v = *(const float4*)(src + off);
    *(__half2*)(dst + off)     = __floats2half2_rn(v.x, v.y);
    *(__half2*)(dst + off + 2) = __floats2half2_rn(v.z, v.w);
}

// ---------------------------------------------------------------------------
// HMMA GEMM: C[4096,1024] = A[4096,1024] @ W[1024,1024]^T + bias
// CTA: 128 threads, tile 128(M)x64(N), 4 warps (2Mx2N), warp tile 64x32.
// BK=64, 2-stage cp.async pipeline, 4 CTAs/SM, one barrier per chunk.
// ---------------------------------------------------------------------------
__device__ __forceinline__ void load_chunk(uint32_t stage_base,
    const __half* __restrict__ A, const __half* __restrict__ Wz,
    int mBase, int nBase, int chunk, int tid)
{
    const __half* Ab = A  + (size_t)mBase * DD + chunk * 64;
    const __half* Bb = Wz + (size_t)nBase * DD + chunk * 64;
    #pragma unroll
    for (int j = 0; j < 8; j++) {
        int idx = tid + j * 128;
        int row = idx >> 3, g = idx & 7;
        cpasync16(stage_base + row * ROWB + g * 16, Ab + (size_t)row * DD + g * 8);
    }
    #pragma unroll
    for (int j = 0; j < 4; j++) {
        int idx = tid + j * 128;
        int row = idx >> 3, g = idx & 7;
        cpasync16(stage_base + A_BYTES + row * ROWB + g * 16, Bb + (size_t)row * DD + g * 8);
    }
}

__global__ __launch_bounds__(128, 4) void mma_gemm(
    const __half* __restrict__ A, const __half* __restrict__ W,
    const float* b0p, const float* b1p, const float* b2p,
    float* o0, __half* h0, __half* h1, __half* h2, int half_out)
{
    extern __shared__ char sm_raw[];
    const uint32_t smem = smem_u32(sm_raw);

    const int tid = threadIdx.x;
    const int wid = tid >> 5, lid = tid & 31;
    const int warpM = wid >> 1;
    const int warpN = wid & 1;
    const int nBase = blockIdx.x * 64;
    const int mBase = blockIdx.y * 128;
    const int z = blockIdx.z;
    const __half* Wz = W + (size_t)z * DD * DD;
    const float* bias = (z == 0) ? b0p : (z == 1) ? b1p : b2p;

    float acc[4][4][4];
    #pragma unroll
    for (int mi = 0; mi < 4; mi++)
        #pragma unroll
        for (int nj = 0; nj < 4; nj++)
            #pragma unroll
            for (int e = 0; e < 4; e++) acc[mi][nj][e] = 0.f;

    const uint32_t aOff = (uint32_t)(warpM * 64 + (lid & 15)) * ROWB + ((lid >> 4) << 4);
    const uint32_t bOff = A_BYTES +
        (uint32_t)(warpN * 32 + (lid & 7) + ((lid >> 4) << 3)) * ROWB + (((lid >> 3) & 1) << 4);

    load_chunk(smem, A, Wz, mBase, nBase, 0, tid);
    cp_commit();

    for (int i = 0; i < NCH; i++) {
        const uint32_t st = smem + (i & 1) * STAGE_B;
        cp_wait0();
        __syncthreads();

        if (i + 1 < NCH)
            load_chunk(smem + ((i + 1) & 1) * STAGE_B, A, Wz, mBase, nBase, i + 1, tid);
        cp_commit();

        #pragma unroll
        for (int kp = 0; kp < 4; kp++) {
            const uint32_t kOff = kp * 32;
            uint32_t af[4][4], bf[2][4];
            #pragma unroll
            for (int mi = 0; mi < 4; mi++)
                ldmx4(af[mi], st + aOff + mi * (16 * ROWB) + kOff);
            #pragma unroll
            for (int g = 0; g < 2; g++)
                ldmx4(bf[g], st + bOff + g * (16 * ROWB) + kOff);
            #pragma unroll
            for (int mi = 0; mi < 4; mi++)
                #pragma unroll
                for (int nj = 0; nj < 4; nj++)
                    mma_fp16(acc[mi][nj], af[mi], bf[nj >> 1][(nj & 1) * 2], bf[nj >> 1][(nj & 1) * 2 + 1]);
        }
    }

    const int rBase = mBase + warpM * 64 + (lid >> 2);
    const int cBase = nBase + warpN * 32 + (lid & 3) * 2;
    if (half_out) {
        __half* hp = (z == 0) ? h0 : (z == 1) ? h1 : h2;
        const float sc = (z == 0) ? QSCALE : 1.f;
        #pragma unroll
        for (int mi = 0; mi < 4; mi++) {
            #pragma unroll
            for (int nj = 0; nj < 4; nj++) {
                int col = cBase + nj * 8;
                float bx = bias[col], by = bias[col + 1];
                int r0 = rBase + mi * 16;
                __half2 v0 = __floats2half2_rn((acc[mi][nj][0] + bx) * sc, (acc[mi][nj][1] + by) * sc);
                __half2 v1 = __floats2half2_rn((acc[mi][nj][2] + bx) * sc, (acc[mi][nj][3] + by) * sc);
                *(__half2*)(hp + (size_t)r0 * DD + col)       = v0;
                *(__half2*)(hp + (size_t)(r0 + 8) * DD + col) = v1;
            }
        }
    } else {
        #pragma unroll
        for (int mi = 0; mi < 4; mi++) {
            #pragma unroll
            for (int nj = 0; nj < 4; nj++) {
                int col = cBase + nj * 8;
                float bx = bias[col], by = bias[col + 1];
                int r0 = rBase + mi * 16;
                float2 v0 = { acc[mi][nj][0] + bx, acc[mi][nj][1] + by };
                float2 v1 = { acc[mi][nj][2] + bx, acc[mi][nj][3] + by };
                *(float2*)(o0 + (size_t)r0 * DD + col)       = v0;
                *(float2*)(o0 + (size_t)(r0 + 8) * DD + col) = v1;
            }
        }
    }
}

// ---------------------------------------------------------------------------
// Tensorized causal flash attention (fp16 mma, no-max softmax, log2 domain).
// 256 threads, 8 warps x 16 q-rows, 2 CTAs/SM. exp2 on MUFU.
// R16: row sums via fp32 FADD during exp phase + one epilogue shfl-reduce
// (replaces the ones-column mma: -4 mma per k-tile, FMA pipe was idle).
// Warp-uniform whole-tile causal skip retained.
// ---------------------------------------------------------------------------
__global__ __launch_bounds__(256, 2) void flash_mma()
{
    __shared__ __align__(1024) char sm_f[FSMEM];
    const uint32_t base = smem_u32(sm_f);

    const int tid = threadIdx.x;
    const int wid = tid >> 5, lid = tid & 31;
    const int qt = 15 - blockIdx.x;
    const int h  = blockIdx.y;
    const int b  = blockIdx.z;
    const int qb = qt * 128;
    const int nk = (qt + 1) * 2;
    const int rowMax = qb + wid * 16 + 15;      // warp's last owned q-row

    const __half* qp  = g_qh + (size_t)(b * TT + qb) * DD + h * DH;
    const __half* kp0 = g_kh + (size_t)(b * TT) * DD + h * DH;
    const __half* vp0 = g_vh + (size_t)(b * TT) * DD + h * DH;

    #pragma unroll
    for (int j = 0; j < 4; j++) {
        int idx = tid + j * 256;
        int row = idx >> 3, g = idx & 7;
        cpasync16(base + row * FROW + g * 16, qp + (size_t)row * DD + g * 8);
    }
    cp_commit(); cp_wait0();
    __syncthreads();
    uint32_t qf[4][4];
    const uint32_t qaddr = base + (uint32_t)(wid * 16 + (lid & 15)) * FROW + ((lid >> 4) << 4);
    #pragma unroll
    for (int ks = 0; ks < 4; ks++) ldmx4(qf[ks], qaddr + ks * 32);
    __syncthreads();

    // preload ktile 0
    {
        #pragma unroll
        for (int j = 0; j < 2; j++) {
            int idx = tid + j * 256;
            int row = idx >> 3, g = idx & 7;
            cpasync16(base + row * FROW + g * 16,          kp0 + (size_t)row * DD + g * 8);
            cpasync16(base + FSTG_K + row * FROW + g * 16, vp0 + (size_t)row * DD + g * 8);
        }
        cp_commit();
    }

    float of[8][4];
    #pragma unroll
    for (int t = 0; t < 8; t++)
        #pragma unroll
        for (int e = 0; e < 4; e++) of[t][e] = 0.f;
    float lsum0 = 0.f, lsum1 = 0.f;             // row sums (rows r0, r0+8)

    const uint32_t kfOff = (uint32_t)((lid & 7) + ((lid >> 4) << 3)) * FROW + (((lid >> 3) & 1) << 4);
    const uint32_t vfOff = (uint32_t)((lid & 7) + (((lid >> 3) & 1) << 3)) * FROW + ((lid >> 4) << 4);

    for (int kt = 0; kt < nk; kt++) {
        const int s = kt & 1;
        const int kb = kt * 64;
        __syncthreads();
        if (kt + 1 < nk) {
            const __half* kp = kp0 + (size_t)(kb + 64) * DD;
            const __half* vp = vp0 + (size_t)(kb + 64) * DD;
            uint32_t sb = base + (s ^ 1) * FSTG;
            #pragma unroll
            for (int j = 0; j < 2; j++) {
                int idx = tid + j * 256;
                int row = idx >> 3, g = idx & 7;
                cpasync16(sb + row * FROW + g * 16,          kp + (size_t)row * DD + g * 8);
                cpasync16(sb + FSTG_K + row * FROW + g * 16, vp + (size_t)row * DD + g * 8);
            }
            cp_commit(); cp_wait1();
        } else {
            cp_wait0();
        }
        __syncthreads();

        // warp-uniform whole-tile skip: entire tile above this warp's rows
        if (rowMax < kb) continue;

        const uint32_t st = base + s * FSTG;

        float sf[8][4];
        #pragma unroll
        for (int t = 0; t < 8; t++)
            #pragma unroll
            for (int e = 0; e < 4; e++) sf[t][e] = 0.f;

        #pragma unroll
        for (int ks = 0; ks < 4; ks++) {
            uint32_t bf[4][4];
            #pragma unroll
            for (int t = 0; t < 4; t++)
                ldmx4(bf[t], st + kfOff + t * (16 * FROW) + ks * 32);
            #pragma unroll
            for (int nt = 0; nt < 8; nt++)
                mma_fp16(sf[nt], qf[ks], bf[nt >> 1][(nt & 1) * 2], bf[nt >> 1][(nt & 1) * 2 + 1]);
        }

        if (kb + 63 > qb) {
            const int r0 = qb + wid * 16 + (lid >> 2);
            const int c0 = kb + 2 * (lid & 3);
            #pragma unroll
            for (int nt = 0; nt < 8; nt++)
                #pragma unroll
                for (int e = 0; e < 4; e++) {
                    int col = c0 + nt * 8 + (e & 1);
                    int row = r0 + (e >> 1) * 8;
                    if (col > row) sf[nt][e] = -60.f;
                }
        }

        // P = exp2(S) on MUFU; accumulate fp32 row sums on the idle FMA pipe
        uint32_t pf[8][2];
        #pragma unroll
        for (int nt = 0; nt < 8; nt++) {
            float p0 = exp2_mufu(sf[nt][0]);
            float p1 = exp2_mufu(sf[nt][1]);
            float p2 = exp2_mufu(sf[nt][2]);
            float p3 = exp2_mufu(sf[nt][3]);
            lsum0 += p0 + p1;
            lsum1 += p2 + p3;
            pf[nt][0] = packh2(p0, p1);
            pf[nt][1] = packh2(p2, p3);
        }

        // O += P V (no ones column; 8 mma per ks instead of 9)
        #pragma unroll
        for (int ks = 0; ks < 4; ks++) {
            uint32_t pa[4] = { pf[2*ks][0], pf[2*ks][1], pf[2*ks+1][0], pf[2*ks+1][1] };
            uint32_t vrow = st + FSTG_K + ks * (16 * FROW);
            uint32_t vf[4][4];
            #pragma unroll
            for (int t = 0; t < 4; t++)
                ldmx4t(vf[t], vrow + vfOff + t * 32);
            #pragma unroll
            for (int dt = 0; dt < 8; dt++)
                mma_fp16(of[dt], pa, vf[dt >> 1][(dt & 1) * 2], vf[dt >> 1][(dt & 1) * 2 + 1]);
        }
    }

    // epilogue: lane-reduce row sums over the 4 lanes covering each row
    lsum0 += __shfl_xor_sync(0xffffffffu, lsum0, 1);
    lsum0 += __shfl_xor_sync(0xffffffffu, lsum0, 2);
    lsum1 += __shfl_xor_sync(0xffffffffu, lsum1, 1);
    lsum1 += __shfl_xor_sync(0xffffffffu, lsum1, 2);
    const float inv0 = 1.f / lsum0;
    const float inv1 = 1.f / lsum1;

    const int r = qb + wid * 16 + (lid >> 2);
    const int c = h * DH + 2 * (lid & 3);
    __half* o0 = g_ch + (size_t)(b * TT + r) * DD + c;
    __half* o1 = g_ch + (size_t)(b * TT + r + 8) * DD + c;
    #pragma unroll
    for (int nt = 0; nt < 8; nt++) {
        *(__half2*)(o0 + nt * 8) = __floats2half2_rn(of[nt][0] * inv0, of[nt][1] * inv0);
        *(__half2*)(o1 + nt * 8) = __floats2half2_rn(of[nt][2] * inv1, of[nt][3] * inv1);
    }
}

// ---------------------------------------------------------------------------
extern "C" void kernel_launch(void* const* d_in, const int* in_sizes, int n_in,
                              void* d_out, int out_size)
{
    (void)in_sizes; (void)n_in; (void)out_size;
    const float* x  = (const float*)d_in[0];
    const float* Wq = (const float*)d_in[1];
    const float* bq = (const float*)d_in[2];
    const float* Wk = (const float*)d_in[3];
    const float* bk = (const float*)d_in[4];
    const float* Wv = (const float*)d_in[5];
    const float* bv = (const float*)d_in[6];
    const float* Wo = (const float*)d_in[7];
    const float* bo = (const float*)d_in[8];
    float* out = (float*)d_out;

    __half *xh, *qh, *kh, *vh, *ch, *wbuf, *wobuf;
    cudaGetSymbolAddress((void**)&xh,    g_xh);
    cudaGetSymbolAddress((void**)&qh,    g_qh);
    cudaGetSymbolAddress((void**)&kh,    g_kh);
    cudaGetSymbolAddress((void**)&vh,    g_vh);
    cudaGetSymbolAddress((void**)&ch,    g_ch);
    cudaGetSymbolAddress((void**)&wbuf,  g_wbuf);
    cudaGetSymbolAddress((void**)&wobuf, g_wobuf);

    cudaFuncSetAttribute(mma_gemm,
                         cudaFuncAttributeMaxDynamicSharedMemorySize, GEMM_SMEM);

    // fused prep: x + 4 weights, one launch
    prep_all<<<(NTOK*DD + 4*DD*DD) / 1024, 256>>>(x, Wq, Wk, Wv, Wo);

    // fused QKV projections -> fp16 (Q pre-scaled into log2 domain)
    mma_gemm<<<dim3(DD/64, NTOK/128, 3), 128, GEMM_SMEM>>>(
        xh, wbuf, bq, bk, bv, nullptr, qh, kh, vh, 1);

    // tensorized causal flash attention (writes ctx fp16)
    flash_mma<<<dim3(TT/128, HH, BB), 256>>>();

    // output projection (fp32 out + bias)
    mma_gemm<<<dim3(DD/64, NTOK/128, 1), 128, GEMM_SMEM>>>(
        ch, wobuf, bo, bo, bo, out, nullptr, nullptr, nullptr, 0);
}

// round 17
// speedup vs baseline: 1.0104x; 1.0104x over previous
#include <cuda_runtime.h>
#include <cuda_fp16.h>
#include <math.h>
#include <stdint.h>

#define BB 2
#define TT 2048
#define DD 1024
#define HH 16
#define DH 64
#define NTOK (BB*TT)
#define NCH 16                  // 1024 / 64 K-chunks
#define ROWB 144                // gemm smem row stride bytes (128B data + 16 pad)
#define A_BYTES (128*ROWB)      // 18432
#define STAGE_B (A_BYTES + 64*ROWB)  // 27648
#define GEMM_SMEM (2*STAGE_B)        // 55296
#define QSCALE 0.1803368801f    // log2(e) / sqrt(64)

// flash smem geometry
#define FROW 144
#define FSTG_K 9216
#define FSTG   18432
#define FSMEM  36864

// Scratch (allocation forbidden; __device__ globals are the sanctioned path)
__device__ __half g_xh[NTOK*DD];                    // x in fp16
__device__ __half g_qh[NTOK*DD];                    // pre-scaled by QSCALE
__device__ __half g_kh[NTOK*DD];
__device__ __half g_vh[NTOK*DD];
__device__ __half g_ch[NTOK*DD];                    // ctx in fp16
__device__ __half g_wbuf[(size_t)3*DD*DD];          // Wq|Wk|Wv fp16
__device__ __half g_wobuf[(size_t)DD*DD];           // Wo fp16

// ---------------------------------------------------------------------------
// PTX helpers
// ---------------------------------------------------------------------------
__device__ __forceinline__ uint32_t smem_u32(const void* p) {
    uint32_t a;
    asm("{ .reg .u64 t; cvta.to.shared.u64 t, %1; cvt.u32.u64 %0, t; }" : "=r"(a) : "l"(p));
    return a;
}
__device__ __forceinline__ void cpasync16(uint32_t saddr, const void* gaddr) {
    asm volatile("cp.async.cg.shared.global [%0], [%1], 16;" :: "r"(saddr), "l"(gaddr) : "memory");
}
__device__ __forceinline__ void cp_commit() { asm volatile("cp.async.commit_group;" ::: "memory"); }
__device__ __forceinline__ void cp_wait0()  { asm volatile("cp.async.wait_group 0;" ::: "memory"); }
__device__ __forceinline__ void cp_wait1()  { asm volatile("cp.async.wait_group 1;" ::: "memory"); }

__device__ __forceinline__ void ldmx4(uint32_t* r, uint32_t addr) {
    asm volatile("ldmatrix.sync.aligned.m8n8.x4.shared.b16 {%0,%1,%2,%3}, [%4];"
                 : "=r"(r[0]), "=r"(r[1]), "=r"(r[2]), "=r"(r[3]) : "r"(addr));
}
__device__ __forceinline__ void ldmx4t(uint32_t* r, uint32_t addr) {
    asm volatile("ldmatrix.sync.aligned.m8n8.x4.trans.shared.b16 {%0,%1,%2,%3}, [%4];"
                 : "=r"(r[0]), "=r"(r[1]), "=r"(r[2]), "=r"(r[3]) : "r"(addr));
}
__device__ __forceinline__ void ldmx2t(uint32_t* r, uint32_t addr) {
    asm volatile("ldmatrix.sync.aligned.m8n8.x2.trans.shared.b16 {%0,%1}, [%2];"
                 : "=r"(r[0]), "=r"(r[1]) : "r"(addr));
}
__device__ __forceinline__ void mma_fp16(float* c, const uint32_t* a, uint32_t b0, uint32_t b1) {
    asm volatile(
        "mma.sync.aligned.m16n8k16.row.col.f32.f16.f16.f32 "
        "{%0,%1,%2,%3}, {%4,%5,%6,%7}, {%8,%9}, {%0,%1,%2,%3};"
        : "+f"(c[0]), "+f"(c[1]), "+f"(c[2]), "+f"(c[3])
        : "r"(a[0]), "r"(a[1]), "r"(a[2]), "r"(a[3]), "r"(b0), "r"(b1));
}
__device__ __forceinline__ uint32_t packh2(float lo, float hi) {
    uint32_t u;
    asm("cvt.rn.f16x2.f32 %0, %1, %2;" : "=r"(u) : "f"(hi), "f"(lo));
    return u;
}
__device__ __forceinline__ float exp2_mufu(float y) {
    float r;
    asm("ex2.approx.f32 %0, %1;" : "=f"(r) : "f"(y));
    return r;
}

// ---------------------------------------------------------------------------
// Fused prep: fp32 -> fp16 for x + all four weight matrices, one launch.
// ---------------------------------------------------------------------------
__global__ void prep_all(const float* __restrict__ x,
                         const float* __restrict__ Wq, const float* __restrict__ Wk,
                         const float* __restrict__ Wv, const float* __restrict__ Wo)
{
    int i = (blockIdx.x * 256 + threadIdx.x) * 4;
    const float* src;
    __half* dst;
    int off;
    if (i < NTOK*DD) {
        src = x; dst = g_xh; off = i;
    } else {
        int j = i - NTOK*DD;
        int w = j >> 20;
        off = j & ((1 << 20) - 1);
        src = (w == 0) ? Wq : (w == 1) ? Wk : (w == 2) ? Wv : Wo;
        dst = (w == 3) ? g_wobuf : g_wbuf + (size_t)w * DD * DD;
    }
    float4 v = *(const float4*)(src + off);
    *(__half2*)(dst + off)     = __floats2half2_rn(v.x, v.y);
    *(__half2*)(dst + off + 2) = __floats2half2_rn(v.z, v.w);
}

// ---------------------------------------------------------------------------
// HMMA GEMM: C[4096,1024] = A[4096,1024] @ W[1024,1024]^T + bias
// CTA: 128 threads, tile 128(M)x64(N), 4 warps (2Mx2N), warp tile 64x32.
// BK=64, 2-stage cp.async pipeline, 4 CTAs/SM, one barrier per chunk.
// ---------------------------------------------------------------------------
__device__ __forceinline__ void load_chunk(uint32_t stage_base,
    const __half* __restrict__ A, const __half* __restrict__ Wz,
    int mBase, int nBase, int chunk, int tid)
{
    const __half* Ab = A  + (size_t)mBase * DD + chunk * 64;
    const __half* Bb = Wz + (size_t)nBase * DD + chunk * 64;
    #pragma unroll
    for (int j = 0; j < 8; j++) {
        int idx = tid + j * 128;
        int row = idx >> 3, g = idx & 7;
        cpasync16(stage_base + row * ROWB + g * 16, Ab + (size_t)row * DD + g * 8);
    }
    #pragma unroll
    for (int j = 0; j < 4; j++) {
        int idx = tid + j * 128;
        int row = idx >> 3, g = idx & 7;
        cpasync16(stage_base + A_BYTES + row * ROWB + g * 16, Bb + (size_t)row * DD + g * 8);
    }
}

__global__ __launch_bounds__(128, 4) void mma_gemm(
    const __half* __restrict__ A, const __half* __restrict__ W,
    const float* b0p, const float* b1p, const float* b2p,
    float* o0, __half* h0, __half* h1, __half* h2, int half_out)
{
    extern __shared__ char sm_raw[];
    const uint32_t smem = smem_u32(sm_raw);

    const int tid = threadIdx.x;
    const int wid = tid >> 5, lid = tid & 31;
    const int warpM = wid >> 1;
    const int warpN = wid & 1;
    const int nBase = blockIdx.x * 64;
    const int mBase = blockIdx.y * 128;
    const int z = blockIdx.z;
    const __half* Wz = W + (size_t)z * DD * DD;
    const float* bias = (z == 0) ? b0p : (z == 1) ? b1p : b2p;

    float acc[4][4][4];
    #pragma unroll
    for (int mi = 0; mi < 4; mi++)
        #pragma unroll
        for (int nj = 0; nj < 4; nj++)
            #pragma unroll
            for (int e = 0; e < 4; e++) acc[mi][nj][e] = 0.f;

    const uint32_t aOff = (uint32_t)(warpM * 64 + (lid & 15)) * ROWB + ((lid >> 4) << 4);
    const uint32_t bOff = A_BYTES +
        (uint32_t)(warpN * 32 + (lid & 7) + ((lid >> 4) << 3)) * ROWB + (((lid >> 3) & 1) << 4);

    load_chunk(smem, A, Wz, mBase, nBase, 0, tid);
    cp_commit();

    for (int i = 0; i < NCH; i++) {
        const uint32_t st = smem + (i & 1) * STAGE_B;
        cp_wait0();
        __syncthreads();

        if (i + 1 < NCH)
            load_chunk(smem + ((i + 1) & 1) * STAGE_B, A, Wz, mBase, nBase, i + 1, tid);
        cp_commit();

        #pragma unroll
        for (int kp = 0; kp < 4; kp++) {
            const uint32_t kOff = kp * 32;
            uint32_t af[4][4], bf[2][4];
            #pragma unroll
            for (int mi = 0; mi < 4; mi++)
                ldmx4(af[mi], st + aOff + mi * (16 * ROWB) + kOff);
            #pragma unroll
            for (int g = 0; g < 2; g++)
                ldmx4(bf[g], st + bOff + g * (16 * ROWB) + kOff);
            #pragma unroll
            for (int mi = 0; mi < 4; mi++)
                #pragma unroll
                for (int nj = 0; nj < 4; nj++)
                    mma_fp16(acc[mi][nj], af[mi], bf[nj >> 1][(nj & 1) * 2], bf[nj >> 1][(nj & 1) * 2 + 1]);
        }
    }

    const int rBase = mBase + warpM * 64 + (lid >> 2);
    const int cBase = nBase + warpN * 32 + (lid & 3) * 2;
    if (half_out) {
        __half* hp = (z == 0) ? h0 : (z == 1) ? h1 : h2;
        const float sc = (z == 0) ? QSCALE : 1.f;
        #pragma unroll
        for (int mi = 0; mi < 4; mi++) {
            #pragma unroll
            for (int nj = 0; nj < 4; nj++) {
                int col = cBase + nj * 8;
                float bx = bias[col], by = bias[col + 1];
                int r0 = rBase + mi * 16;
                __half2 v0 = __floats2half2_rn((acc[mi][nj][0] + bx) * sc, (acc[mi][nj][1] + by) * sc);
                __half2 v1 = __floats2half2_rn((acc[mi][nj][2] + bx) * sc, (acc[mi][nj][3] + by) * sc);
                *(__half2*)(hp + (size_t)r0 * DD + col)       = v0;
                *(__half2*)(hp + (size_t)(r0 + 8) * DD + col) = v1;
            }
        }
    } else {
        #pragma unroll
        for (int mi = 0; mi < 4; mi++) {
            #pragma unroll
            for (int nj = 0; nj < 4; nj++) {
                int col = cBase + nj * 8;
                float bx = bias[col], by = bias[col + 1];
                int r0 = rBase + mi * 16;
                float2 v0 = { acc[mi][nj][0] + bx, acc[mi][nj][1] + by };
                float2 v1 = { acc[mi][nj][2] + bx, acc[mi][nj][3] + by };
                *(float2*)(o0 + (size_t)r0 * DD + col)       = v0;
                *(float2*)(o0 + (size_t)(r0 + 8) * DD + col) = v1;
            }
        }
    }
}

// ---------------------------------------------------------------------------
// Tensorized causal flash attention (fp16 mma, no-max softmax, log2 domain).
// 256 threads, 8 warps x 16 q-rows, 2 CTAs/SM. exp2 on MUFU.
// Ones-column row sums via PV mma (best-measured variant).
// Warp-uniform whole-tile causal skip.
// ---------------------------------------------------------------------------
__global__ __launch_bounds__(256, 2) void flash_mma()
{
    __shared__ __align__(1024) char sm_f[FSMEM];
    const uint32_t base = smem_u32(sm_f);

    const int tid = threadIdx.x;
    const int wid = tid >> 5, lid = tid & 31;
    const int qt = 15 - blockIdx.x;
    const int h  = blockIdx.y;
    const int b  = blockIdx.z;
    const int qb = qt * 128;
    const int nk = (qt + 1) * 2;
    const int rowMax = qb + wid * 16 + 15;      // warp's last owned q-row

    const __half* qp  = g_qh + (size_t)(b * TT + qb) * DD + h * DH;
    const __half* kp0 = g_kh + (size_t)(b * TT) * DD + h * DH;
    const __half* vp0 = g_vh + (size_t)(b * TT) * DD + h * DH;

    #pragma unroll
    for (int j = 0; j < 4; j++) {
        int idx = tid + j * 256;
        int row = idx >> 3, g = idx & 7;
        cpasync16(base + row * FROW + g * 16, qp + (size_t)row * DD + g * 8);
    }
    cp_commit(); cp_wait0();
    __syncthreads();
    uint32_t qf[4][4];
    const uint32_t qaddr = base + (uint32_t)(wid * 16 + (lid & 15)) * FROW + ((lid >> 4) << 4);
    #pragma unroll
    for (int ks = 0; ks < 4; ks++) ldmx4(qf[ks], qaddr + ks * 32);
    __syncthreads();

    if (tid < 128) {
        int s = tid >> 6, r = tid & 63;
        uint4 ones = { 0x3C003C00u, 0x3C003C00u, 0x3C003C00u, 0x3C003C00u };
        *(uint4*)(sm_f + s * FSTG + FSTG_K + r * FROW + 128) = ones;
    }

    {
        #pragma unroll
        for (int j = 0; j < 2; j++) {
            int idx = tid + j * 256;
            int row = idx >> 3, g = idx & 7;
            cpasync16(base + row * FROW + g * 16,          kp0 + (size_t)row * DD + g * 8);
            cpasync16(base + FSTG_K + row * FROW + g * 16, vp0 + (size_t)row * DD + g * 8);
        }
        cp_commit();
    }

    float of[9][4];
    #pragma unroll
    for (int t = 0; t < 9; t++)
        #pragma unroll
        for (int e = 0; e < 4; e++) of[t][e] = 0.f;

    const uint32_t kfOff = (uint32_t)((lid & 7) + ((lid >> 4) << 3)) * FROW + (((lid >> 3) & 1) << 4);
    const uint32_t vfOff = (uint32_t)((lid & 7) + (((lid >> 3) & 1) << 3)) * FROW + ((lid >> 4) << 4);
    const uint32_t vsOff = (uint32_t)((lid & 7) + (((lid >> 3) & 1) << 3)) * FROW + 128;

    for (int kt = 0; kt < nk; kt++) {
        const int s = kt & 1;
        const int kb = kt * 64;
        __syncthreads();
        if (kt + 1 < nk) {
            const __half* kp = kp0 + (size_t)(kb + 64) * DD;
            const __half* vp = vp0 + (size_t)(kb + 64) * DD;
            uint32_t sb = base + (s ^ 1) * FSTG;
            #pragma unroll
            for (int j = 0; j < 2; j++) {
                int idx = tid + j * 256;
                int row = idx >> 3, g = idx & 7;
                cpasync16(sb + row * FROW + g * 16,          kp + (size_t)row * DD + g * 8);
                cpasync16(sb + FSTG_K + row * FROW + g * 16, vp + (size_t)row * DD + g * 8);
            }
            cp_commit(); cp_wait1();
        } else {
            cp_wait0();
        }
        __syncthreads();

        // warp-uniform whole-tile skip: entire tile above this warp's rows
        if (rowMax < kb) continue;

        const uint32_t st = base + s * FSTG;

        float sf[8][4];
        #pragma unroll
        for (int t = 0; t < 8; t++)
            #pragma unroll
            for (int e = 0; e < 4; e++) sf[t][e] = 0.f;

        #pragma unroll
        for (int ks = 0; ks < 4; ks++) {
            uint32_t bf[4][4];
            #pragma unroll
            for (int t = 0; t < 4; t++)
                ldmx4(bf[t], st + kfOff + t * (16 * FROW) + ks * 32);
            #pragma unroll
            for (int nt = 0; nt < 8; nt++)
                mma_fp16(sf[nt], qf[ks], bf[nt >> 1][(nt & 1) * 2], bf[nt >> 1][(nt & 1) * 2 + 1]);
        }

        if (kb + 63 > qb) {
            const int r0 = qb + wid * 16 + (lid >> 2);
            const int c0 = kb + 2 * (lid & 3);
            #pragma unroll
            for (int nt = 0; nt < 8; nt++)
                #pragma unroll
                for (int e = 0; e < 4; e++) {
                    int col = c0 + nt * 8 + (e & 1);
                    int row = r0 + (e >> 1) * 8;
                    if (col > row) sf[nt][e] = -60.f;
                }
        }

        // P = exp2(S): entirely on MUFU
        uint32_t pf[8][2];
        #pragma unroll
        for (int nt = 0; nt < 8; nt++) {
            float p0 = exp2_mufu(sf[nt][0]);
            float p1 = exp2_mufu(sf[nt][1]);
            float p2 = exp2_mufu(sf[nt][2]);
            float p3 = exp2_mufu(sf[nt][3]);
            pf[nt][0] = packh2(p0, p1);
            pf[nt][1] = packh2(p2, p3);
        }

        #pragma unroll
        for (int ks = 0; ks < 4; ks++) {
            uint32_t pa[4] = { pf[2*ks][0], pf[2*ks][1], pf[2*ks+1][0], pf[2*ks+1][1] };
            uint32_t vrow = st + FSTG_K + ks * (16 * FROW);
            uint32_t vf[4][4], vs[2];
            #pragma unroll
            for (int t = 0; t < 4; t++)
                ldmx4t(vf[t], vrow + vfOff + t * 32);
            ldmx2t(vs, vrow + vsOff);
            #pragma unroll
            for (int dt = 0; dt < 8; dt++)
                mma_fp16(of[dt], pa, vf[dt >> 1][(dt & 1) * 2], vf[dt >> 1][(dt & 1) * 2 + 1]);
            mma_fp16(of[8], pa, vs[0], vs[1]);
        }
    }

    const float inv0 = 1.f / of[8][0];
    const float inv1 = 1.f / of[8][2];
    const int r = qb + wid * 16 + (lid >> 2);
    const int c = h * DH + 2 * (lid & 3);
    __half* o0 = g_ch + (size_t)(b * TT + r) * DD + c;
    __half* o1 = g_ch + (size_t)(b * TT + r + 8) * DD + c;
    #pragma unroll
    for (int nt = 0; nt < 8; nt++) {
        *(__half2*)(o0 + nt * 8) = __floats2half2_rn(of[nt][0] * inv0, of[nt][1] * inv0);
        *(__half2*)(o1 + nt * 8) = __floats2half2_rn(of[nt][2] * inv1, of[nt][3] * inv1);
    }
}

// ---------------------------------------------------------------------------
extern "C" void kernel_launch(void* const* d_in, const int* in_sizes, int n_in,
                              void* d_out, int out_size)
{
    (void)in_sizes; (void)n_in; (void)out_size;
    const float* x  = (const float*)d_in[0];
    const float* Wq = (const float*)d_in[1];
    const float* bq = (const float*)d_in[2];
    const float* Wk = (const float*)d_in[3];
    const float* bk = (const float*)d_in[4];
    const float* Wv = (const float*)d_in[5];
    const float* bv = (const float*)d_in[6];
    const float* Wo = (const float*)d_in[7];
    const float* bo = (const float*)d_in[8];
    float* out = (float*)d_out;

    __half *xh, *qh, *kh, *vh, *ch, *wbuf, *wobuf;
    cudaGetSymbolAddress((void**)&xh,    g_xh);
    cudaGetSymbolAddress((void**)&qh,    g_qh);
    cudaGetSymbolAddress((void**)&kh,    g_kh);
    cudaGetSymbolAddress((void**)&vh,    g_vh);
    cudaGetSymbolAddress((void**)&ch,    g_ch);
    cudaGetSymbolAddress((void**)&wbuf,  g_wbuf);
    cudaGetSymbolAddress((void**)&wobuf, g_wobuf);

    cudaFuncSetAttribute(mma_gemm,
                         cudaFuncAttributeMaxDynamicSharedMemorySize, GEMM_SMEM);

    // fused prep: x + 4 weights, one launch
    prep_all<<<(NTOK*DD + 4*DD*DD) / 1024, 256>>>(x, Wq, Wk, Wv, Wo);

    // fused QKV projections -> fp16 (Q pre-scaled into log2 domain)
    mma_gemm<<<dim3(DD/64, NTOK/128, 3), 128, GEMM_SMEM>>>(
        xh, wbuf, bq, bk, bv, nullptr, qh, kh, vh, 1);

    // tensorized causal flash attention (writes ctx fp16)
    flash_mma<<<dim3(TT/128, HH, BB), 256>>>();

    // output projection (fp32 out + bias)
    mma_gemm<<<dim3(DD/64, NTOK/128, 1), 128, GEMM_SMEM>>>(
        ch, wobuf, bo, bo, bo, out, nullptr, nullptr, nullptr, 0);
}